// round 16
// baseline (speedup 1.0000x reference)
#include <cuda_runtime.h>
#include <cuda_fp16.h>
#include <cstdint>
#include <math.h>

// ============================ config ============================
#define NTHREADS 256
#define TILE_M   256          // 8 warps x m=32, persistent CTAs

// f16 row strides (bytes); stride/4 mod 32 == 4 -> conflict-free ldmatrix
#define WROW0_B  144          // K=64  (L0)
#define WROW1_B  272          // K=128 (L1,L2,L3,L5,head)
#define WROW4_B  400          // K=192 (L4)

// g_wscratch word offsets per slot {L0,L1,L2,L3,L4,L5,head} (R10 layout)
__device__ __constant__ int SLOT_OFF[7] = {0, 4608, 13312, 22016, 30720, 43520, 52224};
#define WSCRATCH_WORDS 52768
__device__ __align__(16) uint32_t g_wscratch[WSCRATCH_WORDS];
__device__ __align__(16) float    g_biasg[6 * 128];

// smem layout (bytes): linear image of g_wscratch + bias + warp screw scratch
#define W0_OFF     0          // 18432
#define W1_OFF     18432      // 34816
#define W2_OFF     53248
#define W3_OFF     88064
#define W4_OFF     122880     // 51200
#define W5_OFF     174080
#define WH_OFF     208896     // 2176
#define SBIAS_OFF  211072     // 768 f32
#define SCREW_OFF  214144     // 8 warps x 1024 B
#define SMEM_BYTES 222336

// ============================ helpers ============================
__device__ __forceinline__ uint32_t smem_to_u32(const void* p) {
    uint32_t a;
    asm("{ .reg .u64 t; cvta.to.shared.u64 t, %1; cvt.u32.u64 %0, t; }" : "=r"(a) : "l"(p));
    return a;
}

__device__ __forceinline__ void ldmx4(uint32_t& r0, uint32_t& r1, uint32_t& r2, uint32_t& r3, uint32_t addr) {
    asm volatile("ldmatrix.sync.aligned.m8n8.x4.shared.b16 {%0,%1,%2,%3}, [%4];"
        : "=r"(r0), "=r"(r1), "=r"(r2), "=r"(r3) : "r"(addr));
}

// f16 inputs, f16 accumulators (C packed f16x2)
__device__ __forceinline__ void mma_h(uint32_t (&c)[2],
    uint32_t a0, uint32_t a1, uint32_t a2, uint32_t a3, uint32_t b0, uint32_t b1) {
    asm volatile("mma.sync.aligned.m16n8k16.row.col.f16.f16.f16.f16 "
        "{%0,%1}, {%2,%3,%4,%5}, {%6,%7}, {%0,%1};"
        : "+r"(c[0]), "+r"(c[1])
        : "r"(a0), "r"(a1), "r"(a2), "r"(a3), "r"(b0), "r"(b1));
}

// f16 inputs, f32 accumulators (head)
__device__ __forceinline__ void mma_hf32(float (&c)[4],
    uint32_t a0, uint32_t a1, uint32_t a2, uint32_t a3, uint32_t b0, uint32_t b1) {
    asm volatile("mma.sync.aligned.m16n8k16.row.col.f32.f16.f16.f32 "
        "{%0,%1,%2,%3}, {%4,%5,%6,%7}, {%8,%9}, {%0,%1,%2,%3};"
        : "+f"(c[0]), "+f"(c[1]), "+f"(c[2]), "+f"(c[3])
        : "r"(a0), "r"(a1), "r"(a2), "r"(a3), "r"(b0), "r"(b1));
}

__device__ __forceinline__ uint32_t pack_h2(float lo, float hi) {
    __half2 h = __floats2half2_rn(lo, hi);
    return *reinterpret_cast<uint32_t*>(&h);
}

__device__ __forceinline__ uint32_t relu_h2(uint32_t x) {
    __half2 h = *reinterpret_cast<__half2*>(&x);
    h = __hmax2(h, __float2half2_rn(0.0f));
    return *reinterpret_cast<uint32_t*>(&h);
}

__device__ __forceinline__ void cp_async16(uint32_t dst, const void* src) {
    asm volatile("cp.async.cg.shared.global [%0], [%1], 16;" :: "r"(dst), "l"(src));
}
#define CP_COMMIT()   asm volatile("cp.async.commit_group;" ::: "memory")
#define CP_WAIT_ALL() asm volatile("cp.async.wait_all;" ::: "memory")

// weight element fetch (k = element index)
__device__ __forceinline__ float wfetch(int mode, int n, int k, const float* Wa, const float* Wb) {
    if (mode == 0) return __ldg(Wa + n * 128 + k);                   // fan_in 128
    if (mode == 1) return (k < 53) ? __ldg(Wa + n * 53 + k) : 0.0f;  // L0: 53 -> pad 64
    if (mode == 2) {                                                 // L4: concat(53 pad 64, 128)
        if (k < 53) return __ldg(Wa + n * 181 + k);
        if (k < 64) return 0.0f;
        return __ldg(Wa + n * 181 + (k - 11));
    }
    // mode 3: head rows = [Wv0..2, Wr0..2, 0, 0]
    if (n < 3) return __ldg(Wa + n * 128 + k);
    if (n < 6) return __ldg(Wb + (n - 3) * 128 + k);
    return 0.0f;
}

// ============================ prep kernel ============================
__global__ void prep_weights(
    const float* W0, const float* W1, const float* W2, const float* W3,
    const float* W4, const float* W5, const float* Wv, const float* Wr,
    const float* b0, const float* b1, const float* b2, const float* b3,
    const float* b4, const float* b5)
{
    int slot = blockIdx.y;
    int idx = blockIdx.x * 256 + threadIdx.x;
    uint32_t* dst = g_wscratch + SLOT_OFF[slot];

    const float *Wa = nullptr, *Wb = nullptr, *bb = nullptr;
    int mode = 0, rows = 128, wroww = 68, datw = 64;
    switch (slot) {
        case 0: Wa = W0; mode = 1; wroww = 36;  datw = 32; bb = b0; break;
        case 1: Wa = W1; mode = 0; wroww = 68;  datw = 64; bb = b1; break;
        case 2: Wa = W2; mode = 0; wroww = 68;  datw = 64; bb = b2; break;
        case 3: Wa = W3; mode = 0; wroww = 68;  datw = 64; bb = b3; break;
        case 4: Wa = W4; mode = 2; wroww = 100; datw = 96; bb = b4; break;
        case 5: Wa = W5; mode = 0; wroww = 68;  datw = 64; bb = b5; break;
        case 6: Wa = Wv; Wb = Wr; mode = 3; rows = 8; wroww = 68; datw = 64; break;
    }
    int words = rows * wroww;
    if (idx < words) {
        int n = idx / wroww;
        int kpos = idx - n * wroww;
        float f0 = 0.0f, f1 = 0.0f;
        if (kpos < datw) {
            int k = kpos * 2;
            f0 = wfetch(mode, n, k,     Wa, Wb);
            f1 = wfetch(mode, n, k + 1, Wa, Wb);
        }
        dst[idx] = pack_h2(f0, f1);
    } else if (bb && (idx - words) < 128) {
        g_biasg[slot * 128 + (idx - words)] = __ldg(bb + (idx - words));
    }
}

// ============================ main kernel pieces ============================
// closed-form positional-encoding feature c of point g
__device__ __forceinline__ float enc_val(const float* __restrict__ wcode, int g, int c,
                                         float p0, float p1, float p2) {
    if (c < 42) {
        int cc = (c < 21) ? c : c - 21;
        int i = cc / 7;
        int j = cc - i * 7;
        float p = (i == 0) ? p0 : ((i == 1) ? p1 : p2);
        float s = 6.283185307179586f * p * (float)(1 << j);
        return (c < 21) ? __sinf(s) : __cosf(s);
    }
    if (c < 45) return (c == 42) ? p0 : ((c == 43) ? p1 : p2);
    if (c < 53) return __ldg(wcode + (long)g * 8 + (c - 45));
    return 0.0f;
}

// one dense layer, kc-outer / nt-inner
template<int NCH, int ENCCH, int WROWB>
__device__ __forceinline__ void do_layer(uint32_t (&C)[2][16][2],
    const uint32_t (&Aenc)[2][16], const uint32_t (&Aact)[2][32],
    uint32_t wbase, const float* sbias, int lane)
{
    const int nb = (lane & 3) * 2;
    #pragma unroll
    for (int nt = 0; nt < 16; ++nt) {
        uint32_t bp = pack_h2(sbias[nt * 8 + nb], sbias[nt * 8 + nb + 1]);
        C[0][nt][0] = bp; C[0][nt][1] = bp;
        C[1][nt][0] = bp; C[1][nt][1] = bp;
    }
    const uint32_t baddr = wbase + (uint32_t)(lane & 7) * WROWB + (uint32_t)(lane >> 3) * 16u;
    #pragma unroll
    for (int kc = 0; kc < NCH; kc += 2) {
        const uint32_t* A00 = (kc     < ENCCH) ? &Aenc[0][kc * 4]       : &Aact[0][(kc - ENCCH) * 4];
        const uint32_t* A01 = (kc     < ENCCH) ? &Aenc[1][kc * 4]       : &Aact[1][(kc - ENCCH) * 4];
        const uint32_t* A10 = (kc + 1 < ENCCH) ? &Aenc[0][(kc + 1) * 4] : &Aact[0][(kc + 1 - ENCCH) * 4];
        const uint32_t* A11 = (kc + 1 < ENCCH) ? &Aenc[1][(kc + 1) * 4] : &Aact[1][(kc + 1 - ENCCH) * 4];
        const uint32_t kaddr = baddr + (uint32_t)kc * 32u;
        #pragma unroll
        for (int nt = 0; nt < 16; ++nt) {
            uint32_t b0, b1, b2, b3;
            ldmx4(b0, b1, b2, b3, kaddr + (uint32_t)nt * (8u * WROWB));
            mma_h(C[0][nt], A00[0], A00[1], A00[2], A00[3], b0, b1);
            mma_h(C[1][nt], A01[0], A01[1], A01[2], A01[3], b0, b1);
            mma_h(C[0][nt], A10[0], A10[1], A10[2], A10[3], b2, b3);
            mma_h(C[1][nt], A11[0], A11[1], A11[2], A11[3], b2, b3);
        }
    }
}

__device__ __forceinline__ void repack(const uint32_t (&C)[2][16][2], uint32_t (&A)[2][32]) {
    #pragma unroll
    for (int t = 0; t < 2; ++t)
        #pragma unroll
        for (int j = 0; j < 8; ++j) {
            A[t][j*4+0] = relu_h2(C[t][2*j][0]);
            A[t][j*4+1] = relu_h2(C[t][2*j][1]);
            A[t][j*4+2] = relu_h2(C[t][2*j+1][0]);
            A[t][j*4+3] = relu_h2(C[t][2*j+1][1]);
        }
}

extern "C" __global__ void __launch_bounds__(NTHREADS, 1)
se3_warp_mma_kernel(
    const float* __restrict__ positions,
    const float* __restrict__ directions,
    const float* __restrict__ warp_code,
    const float* __restrict__ br,
    const float* __restrict__ bv,
    float* __restrict__ out, int N, int ntiles)
{
    extern __shared__ char smc[];
    const uint32_t sb = smem_to_u32(smc);
    const int tid = threadIdx.x;
    const int lane = tid & 31;
    const int warp = tid >> 5;
    const int warpbase = warp * 32;
    const int q = lane & 3;

    // ---- one-time: stage ALL weights + biases into smem ----
    {
        const uint4* s = (const uint4*)g_wscratch;
        #pragma unroll 4
        for (int i = tid; i < WSCRATCH_WORDS / 4; i += NTHREADS)
            cp_async16(sb + (uint32_t)i * 16u, s + i);
        if (tid < 192)
            cp_async16(sb + SBIAS_OFF + (uint32_t)tid * 16u, ((const uint4*)g_biasg) + tid);
        CP_COMMIT();
        CP_WAIT_ALL();
        __syncthreads();
    }

    const float* sbias = (const float*)(smc + SBIAS_OFF);
    float* wscr = (float*)(smc + SCREW_OFF + warp * 1024);   // warp-private 32x8 f32

    // ---- persistent grid-stride loop over 256-point tiles; NO CTA barriers inside ----
    for (int tile = blockIdx.x; tile < ntiles; tile += gridDim.x) {
        const int tbase = tile * TILE_M;

        // enc A-fragments computed directly in registers (no smem)
        uint32_t Aenc[2][16];
        #pragma unroll
        for (int t = 0; t < 2; ++t) {
            #pragma unroll
            for (int half = 0; half < 2; ++half) {
                int g = tbase + warpbase + 16 * t + (lane >> 2) + 8 * half;
                if (g >= N) g = N - 1;
                float p0 = __ldg(positions + (long)g * 3 + 0);
                float p1 = __ldg(positions + (long)g * 3 + 1);
                float p2 = __ldg(positions + (long)g * 3 + 2);
                #pragma unroll
                for (int kc = 0; kc < 4; ++kc) {
                    int c0 = 16 * kc + 2 * q;
                    Aenc[t][kc * 4 + half] =
                        pack_h2(enc_val(warp_code, g, c0,     p0, p1, p2),
                                enc_val(warp_code, g, c0 + 1, p0, p1, p2));
                    Aenc[t][kc * 4 + 2 + half] =
                        pack_h2(enc_val(warp_code, g, c0 + 8, p0, p1, p2),
                                enc_val(warp_code, g, c0 + 9, p0, p1, p2));
                }
            }
        }

        uint32_t C[2][16][2];
        uint32_t Aact[2][32];

        do_layer<4,  4, WROW0_B>(C, Aenc, Aact, sb + W0_OFF, sbias + 0,   lane); repack(C, Aact);
        do_layer<8,  0, WROW1_B>(C, Aenc, Aact, sb + W1_OFF, sbias + 128, lane); repack(C, Aact);
        do_layer<8,  0, WROW1_B>(C, Aenc, Aact, sb + W2_OFF, sbias + 256, lane); repack(C, Aact);
        do_layer<8,  0, WROW1_B>(C, Aenc, Aact, sb + W3_OFF, sbias + 384, lane); repack(C, Aact);
        do_layer<12, 4, WROW4_B>(C, Aenc, Aact, sb + W4_OFF, sbias + 512, lane); repack(C, Aact);
        do_layer<8,  0, WROW1_B>(C, Aenc, Aact, sb + W5_OFF, sbias + 640, lane); repack(C, Aact);

        // head MMA (f32 accum) -> warp-private screw scatter
        {
            float hc[2][4] = {{0.f,0.f,0.f,0.f},{0.f,0.f,0.f,0.f}};
            const uint32_t baddr = sb + WH_OFF + (uint32_t)(lane & 7) * WROW1_B + (uint32_t)(lane >> 3) * 16u;
            #pragma unroll
            for (int kc = 0; kc < 8; kc += 2) {
                uint32_t b0, b1, b2, b3;
                ldmx4(b0, b1, b2, b3, baddr + (uint32_t)kc * 32u);
                #pragma unroll
                for (int t = 0; t < 2; ++t) {
                    mma_hf32(hc[t], Aact[t][kc*4+0], Aact[t][kc*4+1], Aact[t][kc*4+2], Aact[t][kc*4+3], b0, b1);
                    mma_hf32(hc[t], Aact[t][(kc+1)*4+0], Aact[t][(kc+1)*4+1], Aact[t][(kc+1)*4+2], Aact[t][(kc+1)*4+3], b2, b3);
                }
            }
            __syncwarp();   // previous tile's scratch reads done
            int n0 = q * 2;
            #pragma unroll
            for (int t = 0; t < 2; ++t) {
                int m0 = 16 * t + (lane >> 2);          // warp-local row
                wscr[m0 * 8 + n0]           = hc[t][0];
                wscr[m0 * 8 + n0 + 1]       = hc[t][1];
                wscr[(m0 + 8) * 8 + n0]     = hc[t][2];
                wscr[(m0 + 8) * 8 + n0 + 1] = hc[t][3];
            }
            __syncwarp();
        }

        // SE(3) exp-map epilogue: one lane per point (32 points per warp)
        {
            const int g = tbase + warpbase + lane;
            if (g < N) {
                float vx = wscr[lane*8+0] + __ldg(bv + 0);
                float vy = wscr[lane*8+1] + __ldg(bv + 1);
                float vz = wscr[lane*8+2] + __ldg(bv + 2);
                float wx = wscr[lane*8+3] + __ldg(br + 0);
                float wy = wscr[lane*8+4] + __ldg(br + 1);
                float wz = wscr[lane*8+5] + __ldg(br + 2);

                float ang2 = fmaxf(wx*wx + wy*wy + wz*wz, 1e-4f);
                float ang  = sqrtf(ang2);
                float sa = sinf(ang), ca = cosf(ang);
                float f1 = sa / ang;
                float f2 = (1.0f - ca) / ang2;
                float f3 = (ang - sa) / (ang * ang2);

                float K[3][3] = {{0.f,  wz, -wy},
                                 {-wz, 0.f,  wx},
                                 { wy, -wx, 0.f}};
                float KK[3][3];
                #pragma unroll
                for (int a = 0; a < 3; ++a)
                    #pragma unroll
                    for (int b = 0; b < 3; ++b)
                        KK[a][b] = K[a][0]*K[0][b] + K[a][1]*K[1][b] + K[a][2]*K[2][b];

                float R[3][3], V[3][3];
                #pragma unroll
                for (int a = 0; a < 3; ++a)
                    #pragma unroll
                    for (int b = 0; b < 3; ++b) {
                        float I = (a == b) ? 1.0f : 0.0f;
                        R[a][b] = I + f1*K[a][b] + f2*KK[a][b];
                        V[a][b] = I + f2*K[a][b] + f3*KK[a][b];
                    }
                float T0 = V[0][0]*vx + V[0][1]*vy + V[0][2]*vz;
                float T1 = V[1][0]*vx + V[1][1]*vy + V[1][2]*vz;
                float T2 = V[2][0]*vx + V[2][1]*vy + V[2][2]*vz;

                float px = positions[(long)g*3+0],  py = positions[(long)g*3+1],  pz = positions[(long)g*3+2];
                float dx = directions[(long)g*3+0], dy = directions[(long)g*3+1], dz = directions[(long)g*3+2];

                // M[:3,:3] = R^T, M[:3,3] = T  =>  wp = R^T p + T, wd = R^T d
                float wp0 = R[0][0]*px + R[1][0]*py + R[2][0]*pz + T0;
                float wp1 = R[0][1]*px + R[1][1]*py + R[2][1]*pz + T1;
                float wp2 = R[0][2]*px + R[1][2]*py + R[2][2]*pz + T2;
                float wd0 = R[0][0]*dx + R[1][0]*dy + R[2][0]*dz;
                float wd1 = R[0][1]*dx + R[1][1]*dy + R[2][1]*dz;
                float wd2 = R[0][2]*dx + R[1][2]*dy + R[2][2]*dz;

                wp0 = isnan(wp0) ? px : wp0;
                wp1 = isnan(wp1) ? py : wp1;
                wp2 = isnan(wp2) ? pz : wp2;
                wd0 = isnan(wd0) ? dx : wd0;
                wd1 = isnan(wd1) ? dy : wd1;
                wd2 = isnan(wd2) ? dz : wd2;

                out[(long)g*3+0] = wp0; out[(long)g*3+1] = wp1; out[(long)g*3+2] = wp2;
                long long off = 3LL * N;
                out[off + (long)g*3+0] = wd0; out[off + (long)g*3+1] = wd1; out[off + (long)g*3+2] = wd2;
            }
        }
    }
}

// ============================ launch ============================
extern "C" void kernel_launch(void* const* d_in, const int* in_sizes, int n_in,
                              void* d_out, int out_size) {
    const float* positions  = (const float*)d_in[0];
    const float* directions = (const float*)d_in[1];
    const float* warp_code  = (const float*)d_in[2];
    const float* W0 = (const float*)d_in[3];  const float* b0 = (const float*)d_in[4];
    const float* W1 = (const float*)d_in[5];  const float* b1 = (const float*)d_in[6];
    const float* W2 = (const float*)d_in[7];  const float* b2 = (const float*)d_in[8];
    const float* W3 = (const float*)d_in[9];  const float* b3 = (const float*)d_in[10];
    const float* W4 = (const float*)d_in[11]; const float* b4 = (const float*)d_in[12];
    const float* W5 = (const float*)d_in[13]; const float* b5 = (const float*)d_in[14];
    const float* Wr = (const float*)d_in[15]; const float* br = (const float*)d_in[16];
    const float* Wv = (const float*)d_in[17]; const float* bv = (const float*)d_in[18];

    int N = in_sizes[0] / 3;
    int ntiles = (N + TILE_M - 1) / TILE_M;

    int smCount = 0;
    cudaDeviceGetAttribute(&smCount, cudaDevAttrMultiProcessorCount, 0);
    if (smCount <= 0) smCount = 148;
    int blocks = (ntiles < smCount) ? ntiles : smCount;

    dim3 pgrid(50, 7);
    prep_weights<<<pgrid, 256>>>(W0, W1, W2, W3, W4, W5, Wv, Wr,
                                 b0, b1, b2, b3, b4, b5);

    cudaFuncSetAttribute(se3_warp_mma_kernel,
                         cudaFuncAttributeMaxDynamicSharedMemorySize, SMEM_BYTES);
    se3_warp_mma_kernel<<<blocks, NTHREADS, SMEM_BYTES>>>(
        positions, directions, warp_code, br, bv, (float*)d_out, N, ntiles);
}

// round 17
// speedup vs baseline: 1.0387x; 1.0387x over previous
#include <cuda_runtime.h>
#include <cuda_fp16.h>
#include <cstdint>
#include <math.h>

// ============================ config ============================
#define NTHREADS 128
#define TILE_M   128          // 4 warps x m=32, 2 CTAs/SM

// per-slot row strides in u32 words (all ==4 mod 32 -> conflict-free ldmatrix)
#define WROW0_B  144
#define WROW1_B  272
#define WROW4_B  400

// g_wscratch word offsets per slot {L0,L1,L2,L3,L4,L5,head}
__device__ __constant__ int SLOT_OFF[7] = {0, 4608, 13312, 22016, 30720, 43520, 52224};
__device__ __align__(16) uint32_t g_wscratch[52768];
__device__ __align__(16) float    g_biasg[6 * 128];

// smem layout (bytes)
#define ENC_OFF    0                   // 128 rows x 144 B
#define ENC_ROW_B  144
#define WB0_OFF    18432               // 128 x 400 B (holds L0,L2,L4)
#define WB1_OFF    69632               // 128 x 272 B (holds L1,L3,L5)
#define SBIAS0_OFF 104448              // 128 f32
#define SBIAS1_OFF 104960
#define SCREW_OFF  105472              // 4 warps x 1024 B (warp-private)
#define WH_OFF     109568              // head weights 8 x 272 B
#define SMEM_BYTES 111744              // x2 CTAs = 223488 <= 228KB/SM

// ============================ helpers ============================
__device__ __forceinline__ uint32_t smem_to_u32(const void* p) {
    uint32_t a;
    asm("{ .reg .u64 t; cvta.to.shared.u64 t, %1; cvt.u32.u64 %0, t; }" : "=r"(a) : "l"(p));
    return a;
}

__device__ __forceinline__ void ldmx4(uint32_t& r0, uint32_t& r1, uint32_t& r2, uint32_t& r3, uint32_t addr) {
    asm volatile("ldmatrix.sync.aligned.m8n8.x4.shared.b16 {%0,%1,%2,%3}, [%4];"
        : "=r"(r0), "=r"(r1), "=r"(r2), "=r"(r3) : "r"(addr));
}

// f16 inputs, f16 accumulators
__device__ __forceinline__ void mma_h(uint32_t (&c)[2],
    uint32_t a0, uint32_t a1, uint32_t a2, uint32_t a3, uint32_t b0, uint32_t b1) {
    asm volatile("mma.sync.aligned.m16n8k16.row.col.f16.f16.f16.f16 "
        "{%0,%1}, {%2,%3,%4,%5}, {%6,%7}, {%0,%1};"
        : "+r"(c[0]), "+r"(c[1])
        : "r"(a0), "r"(a1), "r"(a2), "r"(a3), "r"(b0), "r"(b1));
}

// f16 inputs, f32 accumulators (head)
__device__ __forceinline__ void mma_hf32(float (&c)[4],
    uint32_t a0, uint32_t a1, uint32_t a2, uint32_t a3, uint32_t b0, uint32_t b1) {
    asm volatile("mma.sync.aligned.m16n8k16.row.col.f32.f16.f16.f32 "
        "{%0,%1,%2,%3}, {%4,%5,%6,%7}, {%8,%9}, {%0,%1,%2,%3};"
        : "+f"(c[0]), "+f"(c[1]), "+f"(c[2]), "+f"(c[3])
        : "r"(a0), "r"(a1), "r"(a2), "r"(a3), "r"(b0), "r"(b1));
}

__device__ __forceinline__ uint32_t pack_h2(float lo, float hi) {
    __half2 h = __floats2half2_rn(lo, hi);
    return *reinterpret_cast<uint32_t*>(&h);
}

__device__ __forceinline__ uint32_t relu_h2(uint32_t x) {
    __half2 h = *reinterpret_cast<__half2*>(&x);
    h = __hmax2(h, __float2half2_rn(0.0f));
    return *reinterpret_cast<uint32_t*>(&h);
}

__device__ __forceinline__ void cp_async16(uint32_t dst, const void* src) {
    asm volatile("cp.async.cg.shared.global [%0], [%1], 16;" :: "r"(dst), "l"(src));
}
#define CP_COMMIT()   asm volatile("cp.async.commit_group;" ::: "memory")
#define CP_WAIT_ALL() asm volatile("cp.async.wait_all;" ::: "memory")

// weight element fetch (k = element index)
__device__ __forceinline__ float wfetch(int mode, int n, int k, const float* Wa, const float* Wb) {
    if (mode == 0) return __ldg(Wa + n * 128 + k);                   // fan_in 128
    if (mode == 1) return (k < 53) ? __ldg(Wa + n * 53 + k) : 0.0f;  // L0: 53 -> pad 64
    if (mode == 2) {                                                 // L4: concat(53 pad 64, 128)
        if (k < 53) return __ldg(Wa + n * 181 + k);
        if (k < 64) return 0.0f;
        return __ldg(Wa + n * 181 + (k - 11));
    }
    // mode 3: head rows = [Wv0..2, Wr0..2, 0, 0]
    if (n < 3) return __ldg(Wa + n * 128 + k);
    if (n < 6) return __ldg(Wb + (n - 3) * 128 + k);
    return 0.0f;
}

// ============================ prep kernel ============================
__global__ void prep_weights(
    const float* W0, const float* W1, const float* W2, const float* W3,
    const float* W4, const float* W5, const float* Wv, const float* Wr,
    const float* b0, const float* b1, const float* b2, const float* b3,
    const float* b4, const float* b5)
{
    int slot = blockIdx.y;
    int idx = blockIdx.x * 256 + threadIdx.x;
    uint32_t* dst = g_wscratch + SLOT_OFF[slot];

    const float *Wa = nullptr, *Wb = nullptr, *bb = nullptr;
    int mode = 0, rows = 128, wroww = 68, datw = 64;
    switch (slot) {
        case 0: Wa = W0; mode = 1; wroww = 36;  datw = 32; bb = b0; break;
        case 1: Wa = W1; mode = 0; wroww = 68;  datw = 64; bb = b1; break;
        case 2: Wa = W2; mode = 0; wroww = 68;  datw = 64; bb = b2; break;
        case 3: Wa = W3; mode = 0; wroww = 68;  datw = 64; bb = b3; break;
        case 4: Wa = W4; mode = 2; wroww = 100; datw = 96; bb = b4; break;
        case 5: Wa = W5; mode = 0; wroww = 68;  datw = 64; bb = b5; break;
        case 6: Wa = Wv; Wb = Wr; mode = 3; rows = 8; wroww = 68; datw = 64; break;
    }
    int words = rows * wroww;
    if (idx < words) {
        int n = idx / wroww;
        int kpos = idx - n * wroww;
        float f0 = 0.0f, f1 = 0.0f;
        if (kpos < datw) {
            int k = kpos * 2;
            f0 = wfetch(mode, n, k,     Wa, Wb);
            f1 = wfetch(mode, n, k + 1, Wa, Wb);
        }
        dst[idx] = pack_h2(f0, f1);
    } else if (bb && (idx - words) < 128) {
        g_biasg[slot * 128 + (idx - words)] = __ldg(bb + (idx - words));
    }
}

// ============================ main kernel pieces ============================
__device__ __forceinline__ void stage_async(uint32_t dst, const uint32_t* src, int words4,
                                            const float* bsrc, uint32_t sbias_dst, int t, int nthr) {
    const uint4* s = (const uint4*)src;
    #pragma unroll 4
    for (int i = t; i < words4; i += nthr)
        cp_async16(dst + (uint32_t)i * 16u, s + i);
    if (bsrc && t < 32)
        cp_async16(sbias_dst + (uint32_t)t * 16u, (const uint4*)bsrc + t);
}

// one dense layer, kc-outer / nt-inner
template<int NCH, int ENCCH, int WROWB>
__device__ __forceinline__ void do_layer(uint32_t (&C)[2][16][2],
    const uint32_t (&Aenc)[2][16], const uint32_t (&Aact)[2][32],
    uint32_t wbase, const float* sbias, int lane)
{
    const int nb = (lane & 3) * 2;
    #pragma unroll
    for (int nt = 0; nt < 16; ++nt) {
        uint32_t bp = pack_h2(sbias[nt * 8 + nb], sbias[nt * 8 + nb + 1]);
        C[0][nt][0] = bp; C[0][nt][1] = bp;
        C[1][nt][0] = bp; C[1][nt][1] = bp;
    }
    const uint32_t baddr = wbase + (uint32_t)(lane & 7) * WROWB + (uint32_t)(lane >> 3) * 16u;
    #pragma unroll
    for (int kc = 0; kc < NCH; kc += 2) {
        const uint32_t* A00 = (kc     < ENCCH) ? &Aenc[0][kc * 4]       : &Aact[0][(kc - ENCCH) * 4];
        const uint32_t* A01 = (kc     < ENCCH) ? &Aenc[1][kc * 4]       : &Aact[1][(kc - ENCCH) * 4];
        const uint32_t* A10 = (kc + 1 < ENCCH) ? &Aenc[0][(kc + 1) * 4] : &Aact[0][(kc + 1 - ENCCH) * 4];
        const uint32_t* A11 = (kc + 1 < ENCCH) ? &Aenc[1][(kc + 1) * 4] : &Aact[1][(kc + 1 - ENCCH) * 4];
        const uint32_t kaddr = baddr + (uint32_t)kc * 32u;
        #pragma unroll
        for (int nt = 0; nt < 16; ++nt) {
            uint32_t b0, b1, b2, b3;
            ldmx4(b0, b1, b2, b3, kaddr + (uint32_t)nt * (8u * WROWB));
            mma_h(C[0][nt], A00[0], A00[1], A00[2], A00[3], b0, b1);
            mma_h(C[1][nt], A01[0], A01[1], A01[2], A01[3], b0, b1);
            mma_h(C[0][nt], A10[0], A10[1], A10[2], A10[3], b2, b3);
            mma_h(C[1][nt], A11[0], A11[1], A11[2], A11[3], b2, b3);
        }
    }
}

__device__ __forceinline__ void repack(const uint32_t (&C)[2][16][2], uint32_t (&A)[2][32]) {
    #pragma unroll
    for (int t = 0; t < 2; ++t)
        #pragma unroll
        for (int j = 0; j < 8; ++j) {
            A[t][j*4+0] = relu_h2(C[t][2*j][0]);
            A[t][j*4+1] = relu_h2(C[t][2*j][1]);
            A[t][j*4+2] = relu_h2(C[t][2*j+1][0]);
            A[t][j*4+3] = relu_h2(C[t][2*j+1][1]);
        }
}

extern "C" __global__ void __launch_bounds__(NTHREADS, 2)
se3_warp_mma_kernel(
    const float* __restrict__ positions,
    const float* __restrict__ directions,
    const float* __restrict__ warp_code,
    const float* __restrict__ br,
    const float* __restrict__ bv,
    float* __restrict__ out, int N)
{
    extern __shared__ char smc[];
    const uint32_t sb = smem_to_u32(smc);
    const int tid = threadIdx.x;
    const int lane = tid & 31;
    const int warp = tid >> 5;
    const int warpbase = warp * 32;
    const int base = blockIdx.x * TILE_M;

    float* sbias0 = (float*)(smc + SBIAS0_OFF);
    float* sbias1 = (float*)(smc + SBIAS1_OFF);
    float* wscr   = (float*)(smc + SCREW_OFF + warp * 1024);  // warp-private 32x8 f32

    // ---- pre-phase: stage L0 + HEAD async, then encode one point per thread ----
    stage_async(sb + WB0_OFF, g_wscratch + SLOT_OFF[0], 128 * 36 / 4,
                g_biasg + 0 * 128, sb + SBIAS0_OFF, tid, NTHREADS);
    stage_async(sb + WH_OFF, g_wscratch + SLOT_OFF[6], 8 * 68 / 4, nullptr, 0, tid, NTHREADS);
    CP_COMMIT();
    {
        int g = base + tid; if (g >= N) g = N - 1;
        const float TWO_PI = 6.283185307179586f;
        float p0 = positions[g*3+0], p1 = positions[g*3+1], p2 = positions[g*3+2];
        float pp[3] = {p0, p1, p2};
        float vals[64];
        #pragma unroll
        for (int i = 0; i < 3; ++i) {
            float s = TWO_PI * pp[i];
            #pragma unroll
            for (int j = 0; j < 7; ++j) {
                vals[i*7 + j]      = __sinf(s);
                vals[21 + i*7 + j] = __cosf(s);
                s *= 2.0f;
            }
        }
        vals[42] = p0; vals[43] = p1; vals[44] = p2;
        #pragma unroll
        for (int q = 0; q < 8; ++q) vals[45 + q] = warp_code[g*8 + q];
        #pragma unroll
        for (int q = 53; q < 64; ++q) vals[q] = 0.0f;

        char* erow = smc + ENC_OFF + tid * ENC_ROW_B;
        #pragma unroll
        for (int j = 0; j < 32; ++j)
            *(uint32_t*)(erow + j * 4) = pack_h2(vals[2*j], vals[2*j + 1]);
    }
    CP_WAIT_ALL();
    __syncthreads();

    // ---- load enc A fragments (4 k-chunks x 2 m-tiles; live through layer 4) ----
    uint32_t Aenc[2][16];
    {
        const int tileid = lane >> 3;
        const uint32_t arow_off = (uint32_t)((lane & 7) + (tileid & 1) * 8);
        const uint32_t acol = (uint32_t)((tileid >> 1) * 16);
        #pragma unroll
        for (int t = 0; t < 2; ++t) {
            uint32_t abase = sb + ENC_OFF + (uint32_t)(warpbase + t * 16) * ENC_ROW_B
                           + arow_off * ENC_ROW_B + acol;
            #pragma unroll
            for (int ch = 0; ch < 4; ++ch)
                ldmx4(Aenc[t][ch*4+0], Aenc[t][ch*4+1], Aenc[t][ch*4+2], Aenc[t][ch*4+3],
                      abase + (uint32_t)ch * 32u);
        }
    }

    uint32_t C[2][16][2];
    uint32_t Aact[2][32];

    // phase 0: stage L1 -> WB1 (272B rows) ; compute L0 (WB0, 144B rows)
    stage_async(sb + WB1_OFF, g_wscratch + SLOT_OFF[1], 128 * 68 / 4, g_biasg + 128, sb + SBIAS1_OFF, tid, NTHREADS);
    CP_COMMIT();
    do_layer<4, 4, WROW0_B>(C, Aenc, Aact, sb + WB0_OFF, sbias0, lane);
    repack(C, Aact);
    CP_WAIT_ALL();
    __syncthreads();

    // phase 1: stage L2 -> WB0 (272) ; compute L1 (WB1, 272)
    stage_async(sb + WB0_OFF, g_wscratch + SLOT_OFF[2], 128 * 68 / 4, g_biasg + 256, sb + SBIAS0_OFF, tid, NTHREADS);
    CP_COMMIT();
    do_layer<8, 0, WROW1_B>(C, Aenc, Aact, sb + WB1_OFF, sbias1, lane);
    repack(C, Aact);
    CP_WAIT_ALL();
    __syncthreads();

    // phase 2: stage L3 -> WB1 (272) ; compute L2 (WB0, 272)
    stage_async(sb + WB1_OFF, g_wscratch + SLOT_OFF[3], 128 * 68 / 4, g_biasg + 384, sb + SBIAS1_OFF, tid, NTHREADS);
    CP_COMMIT();
    do_layer<8, 0, WROW1_B>(C, Aenc, Aact, sb + WB0_OFF, sbias0, lane);
    repack(C, Aact);
    CP_WAIT_ALL();
    __syncthreads();

    // phase 3: stage L4 -> WB0 (400) ; compute L3 (WB1, 272)
    stage_async(sb + WB0_OFF, g_wscratch + SLOT_OFF[4], 128 * 100 / 4, g_biasg + 512, sb + SBIAS0_OFF, tid, NTHREADS);
    CP_COMMIT();
    do_layer<8, 0, WROW1_B>(C, Aenc, Aact, sb + WB1_OFF, sbias1, lane);
    repack(C, Aact);
    CP_WAIT_ALL();
    __syncthreads();

    // phase 4: stage L5 -> WB1 (272) ; compute L4 (WB0, 400, K = 4 enc + 8 act chunks)
    stage_async(sb + WB1_OFF, g_wscratch + SLOT_OFF[5], 128 * 68 / 4, g_biasg + 640, sb + SBIAS1_OFF, tid, NTHREADS);
    CP_COMMIT();
    do_layer<12, 4, WROW4_B>(C, Aenc, Aact, sb + WB0_OFF, sbias0, lane);
    repack(C, Aact);
    CP_WAIT_ALL();
    __syncthreads();

    // phase 5: compute L5 (WB1, 272) — NO staging, NO trailing CTA barrier
    do_layer<8, 0, WROW1_B>(C, Aenc, Aact, sb + WB1_OFF, sbias1, lane);
    repack(C, Aact);

    // ---- head MMA (f32 accum): weights resident in WH since prologue ----
    {
        float hc[2][4] = {{0.f,0.f,0.f,0.f},{0.f,0.f,0.f,0.f}};
        const uint32_t baddr = sb + WH_OFF + (uint32_t)(lane & 7) * WROW1_B + (uint32_t)(lane >> 3) * 16u;
        #pragma unroll
        for (int kc = 0; kc < 8; kc += 2) {
            uint32_t b0, b1, b2, b3;
            ldmx4(b0, b1, b2, b3, baddr + (uint32_t)kc * 32u);
            #pragma unroll
            for (int t = 0; t < 2; ++t) {
                mma_hf32(hc[t], Aact[t][kc*4+0], Aact[t][kc*4+1], Aact[t][kc*4+2], Aact[t][kc*4+3], b0, b1);
                mma_hf32(hc[t], Aact[t][(kc+1)*4+0], Aact[t][(kc+1)*4+1], Aact[t][(kc+1)*4+2], Aact[t][(kc+1)*4+3], b2, b3);
            }
        }
        int n0 = (lane & 3) * 2;
        #pragma unroll
        for (int t = 0; t < 2; ++t) {
            int m0 = 16 * t + (lane >> 2);            // warp-local row
            wscr[m0 * 8 + n0]           = hc[t][0];
            wscr[m0 * 8 + n0 + 1]       = hc[t][1];
            wscr[(m0 + 8) * 8 + n0]     = hc[t][2];
            wscr[(m0 + 8) * 8 + n0 + 1] = hc[t][3];
        }
        __syncwarp();
    }

    // ---- SE(3) exp-map epilogue: one lane per point (warp-private screw) ----
    {
        const int g = base + warpbase + lane;
        if (g < N) {
            float vx = wscr[lane*8+0] + __ldg(bv + 0);
            float vy = wscr[lane*8+1] + __ldg(bv + 1);
            float vz = wscr[lane*8+2] + __ldg(bv + 2);
            float wx = wscr[lane*8+3] + __ldg(br + 0);
            float wy = wscr[lane*8+4] + __ldg(br + 1);
            float wz = wscr[lane*8+5] + __ldg(br + 2);

            float ang2 = fmaxf(wx*wx + wy*wy + wz*wz, 1e-4f);
            float ang  = sqrtf(ang2);
            float sa = sinf(ang), ca = cosf(ang);
            float f1 = sa / ang;
            float f2 = (1.0f - ca) / ang2;
            float f3 = (ang - sa) / (ang * ang2);

            float K[3][3] = {{0.f,  wz, -wy},
                             {-wz, 0.f,  wx},
                             { wy, -wx, 0.f}};
            float KK[3][3];
            #pragma unroll
            for (int a = 0; a < 3; ++a)
                #pragma unroll
                for (int b = 0; b < 3; ++b)
                    KK[a][b] = K[a][0]*K[0][b] + K[a][1]*K[1][b] + K[a][2]*K[2][b];

            float R[3][3], V[3][3];
            #pragma unroll
            for (int a = 0; a < 3; ++a)
                #pragma unroll
                for (int b = 0; b < 3; ++b) {
                    float I = (a == b) ? 1.0f : 0.0f;
                    R[a][b] = I + f1*K[a][b] + f2*KK[a][b];
                    V[a][b] = I + f2*K[a][b] + f3*KK[a][b];
                }
            float T0 = V[0][0]*vx + V[0][1]*vy + V[0][2]*vz;
            float T1 = V[1][0]*vx + V[1][1]*vy + V[1][2]*vz;
            float T2 = V[2][0]*vx + V[2][1]*vy + V[2][2]*vz;

            float px = positions[g*3+0],  py = positions[g*3+1],  pz = positions[g*3+2];
            float dx = directions[g*3+0], dy = directions[g*3+1], dz = directions[g*3+2];

            // M[:3,:3] = R^T, M[:3,3] = T  =>  wp = R^T p + T, wd = R^T d
            float wp0 = R[0][0]*px + R[1][0]*py + R[2][0]*pz + T0;
            float wp1 = R[0][1]*px + R[1][1]*py + R[2][1]*pz + T1;
            float wp2 = R[0][2]*px + R[1][2]*py + R[2][2]*pz + T2;
            float wd0 = R[0][0]*dx + R[1][0]*dy + R[2][0]*dz;
            float wd1 = R[0][1]*dx + R[1][1]*dy + R[2][1]*dz;
            float wd2 = R[0][2]*dx + R[1][2]*dy + R[2][2]*dz;

            wp0 = isnan(wp0) ? px : wp0;
            wp1 = isnan(wp1) ? py : wp1;
            wp2 = isnan(wp2) ? pz : wp2;
            wd0 = isnan(wd0) ? dx : wd0;
            wd1 = isnan(wd1) ? dy : wd1;
            wd2 = isnan(wd2) ? dz : wd2;

            out[g*3+0] = wp0; out[g*3+1] = wp1; out[g*3+2] = wp2;
            long long off = 3LL * N;
            out[off + g*3+0] = wd0; out[off + g*3+1] = wd1; out[off + g*3+2] = wd2;
        }
    }
}

// ============================ launch ============================
extern "C" void kernel_launch(void* const* d_in, const int* in_sizes, int n_in,
                              void* d_out, int out_size) {
    const float* positions  = (const float*)d_in[0];
    const float* directions = (const float*)d_in[1];
    const float* warp_code  = (const float*)d_in[2];
    const float* W0 = (const float*)d_in[3];  const float* b0 = (const float*)d_in[4];
    const float* W1 = (const float*)d_in[5];  const float* b1 = (const float*)d_in[6];
    const float* W2 = (const float*)d_in[7];  const float* b2 = (const float*)d_in[8];
    const float* W3 = (const float*)d_in[9];  const float* b3 = (const float*)d_in[10];
    const float* W4 = (const float*)d_in[11]; const float* b4 = (const float*)d_in[12];
    const float* W5 = (const float*)d_in[13]; const float* b5 = (const float*)d_in[14];
    const float* Wr = (const float*)d_in[15]; const float* br = (const float*)d_in[16];
    const float* Wv = (const float*)d_in[17]; const float* bv = (const float*)d_in[18];

    int N = in_sizes[0] / 3;
    int blocks = (N + TILE_M - 1) / TILE_M;

    dim3 pgrid(50, 7);
    prep_weights<<<pgrid, 256>>>(W0, W1, W2, W3, W4, W5, Wv, Wr,
                                 b0, b1, b2, b3, b4, b5);

    cudaFuncSetAttribute(se3_warp_mma_kernel,
                         cudaFuncAttributeMaxDynamicSharedMemorySize, SMEM_BYTES);
    se3_warp_mma_kernel<<<blocks, NTHREADS, SMEM_BYTES>>>(
        positions, directions, warp_code, br, bv, (float*)d_out, N);
}